// round 11
// baseline (speedup 1.0000x reference)
#include <cuda_runtime.h>
#include <cuda_fp16.h>
#include <cstdint>

// B=4, S=4096, H=4096, E=64, topK=2 -> T=16384 tokens
#define HDIM 4096
#define EXP  64
#define HC   64                        // K per pipeline chunk
#define NCHUNKS (HDIM / HC)            // 64
#define TOK_PER_BLK 128
#define NTHREADS 512                   // 16 warps: 4m x 2n x 2k

#define A_SPLIT 16384                  // 128 rows x 128 B (64 fp16) SW128
#define B_SPLIT 8192                   // 64 rows x 128 B SW128
#define A_REGION (2 * A_SPLIT)         // 32768
#define B_REGION (2 * B_SPLIT)         // 16384
#define W_CHUNK_BYTES B_REGION
#define BUF_BYTES (A_REGION + B_REGION)        // 49152
#define SMEM_TOTAL (2 * BUF_BYTES)             // 98304

#define WSCALE 64.0f
#define INV_WSCALE 0.015625f

__device__ float g_partials[256];
__device__ unsigned int g_done;
__device__ unsigned char g_w_sw[NCHUNKS * W_CHUNK_BYTES];  // 1 MB, L2-resident

// ---------------- helpers ----------------
__device__ __forceinline__ unsigned sw128(unsigned off) {
    return off ^ ((off >> 3) & 0x70);
}
__device__ __forceinline__ uint32_t h2u(__half2 h) {
    return *reinterpret_cast<uint32_t*>(&h);
}
__device__ __forceinline__ void cp16s(uint32_t dst, const void* src) {
    asm volatile("cp.async.cg.shared.global [%0], [%1], 16;" :: "r"(dst), "l"(src));
}
__device__ __forceinline__ void cp_commit() { asm volatile("cp.async.commit_group;"); }
__device__ __forceinline__ void cp_wait0()  { asm volatile("cp.async.wait_group 0;"); }

__device__ __forceinline__ void ldm4(uint32_t& r0, uint32_t& r1, uint32_t& r2,
                                     uint32_t& r3, uint32_t addr) {
    asm volatile("ldmatrix.sync.aligned.m8n8.x4.shared.b16 {%0,%1,%2,%3}, [%4];"
                 : "=r"(r0), "=r"(r1), "=r"(r2), "=r"(r3) : "r"(addr));
}
__device__ __forceinline__ void mma16816(float* d, const uint32_t* a, const uint32_t* b) {
    asm volatile(
        "mma.sync.aligned.m16n8k16.row.col.f32.f16.f16.f32 "
        "{%0,%1,%2,%3}, {%4,%5,%6,%7}, {%8,%9}, {%0,%1,%2,%3};"
        : "+f"(d[0]), "+f"(d[1]), "+f"(d[2]), "+f"(d[3])
        : "r"(a[0]), "r"(a[1]), "r"(a[2]), "r"(a[3]), "r"(b[0]), "r"(b[1]));
}

// ---------------- prologue: fp16 2-split of (gate_w * 64), SW128, per chunk ----------------
__global__ void prep_w(const float* __restrict__ gw) {
    int idx = blockIdx.x * blockDim.x + threadIdx.x;   // 64c * 64e * 32kp = 131072
    int kp = idx & 31;
    int e  = (idx >> 5) & 63;
    int c  = idx >> 11;
    float2 v = *reinterpret_cast<const float2*>(&gw[(size_t)e * HDIM + c * HC + kp * 2]);
    float ax = v.x * WSCALE, ay = v.y * WSCALE;
    unsigned off = sw128((unsigned)(e * 128 + kp * 4));
    unsigned char* base = g_w_sw + (size_t)c * W_CHUNK_BYTES;
    __half2 h1 = __floats2half2_rn(ax, ay);
    *reinterpret_cast<uint32_t*>(base + off) = h2u(h1);
    float2 f1 = __half22float2(h1);
    __half2 h2 = __floats2half2_rn(ax - f1.x, ay - f1.y);
    *reinterpret_cast<uint32_t*>(base + B_SPLIT + off) = h2u(h2);
}

// ---------------- x staging (512 threads: 4 rows each) ----------------
__device__ __forceinline__ void load_v(float4* v, const float* __restrict__ x,
                                       int tok0, int k0, int kq, int rowbase) {
    #pragma unroll
    for (int i = 0; i < 4; ++i)
        v[i] = *reinterpret_cast<const float4*>(
            &x[(size_t)(tok0 + rowbase + 32 * i) * HDIM + k0 + kq * 4]);
}
__device__ __forceinline__ void stage_x(unsigned char* buf, const float4* v,
                                        int kq, int rowbase) {
    #pragma unroll
    for (int i = 0; i < 4; ++i) {
        int r = rowbase + 32 * i;
        unsigned off = sw128((unsigned)(r * 128 + kq * 8));
        __half2 h1a = __floats2half2_rn(v[i].x, v[i].y);
        __half2 h1b = __floats2half2_rn(v[i].z, v[i].w);
        *reinterpret_cast<uint2*>(buf + off) = make_uint2(h2u(h1a), h2u(h1b));
        float2 f1a = __half22float2(h1a);
        float2 f1b = __half22float2(h1b);
        __half2 h2a = __floats2half2_rn(v[i].x - f1a.x, v[i].y - f1a.y);
        __half2 h2b = __floats2half2_rn(v[i].z - f1b.x, v[i].w - f1b.y);
        *reinterpret_cast<uint2*>(buf + A_SPLIT + off) = make_uint2(h2u(h2a), h2u(h2b));
    }
}

// ---------------- main fused router ----------------
extern __shared__ unsigned char smem_raw[];

__global__ __launch_bounds__(NTHREADS, 1)
void router_kernel(const float* __restrict__ x, float* __restrict__ out, int T) {
    const int tid  = threadIdx.x;
    const int lane = tid & 31;
    const int warp = tid >> 5;          // 0..15
    const int tok0 = blockIdx.x * TOK_PER_BLK;
    const uint32_t sb = (uint32_t)__cvta_generic_to_shared(smem_raw);

    // staging coords (all 512 threads)
    const int kq      = tid & 15;
    const int rowbase = tid >> 4;       // 0..31, rows rowbase + 32*i
    float4 v[4];

    // consumer coords: warp = 4m x 2n x 2k
    const int mbase = (warp & 3) * 32;
    const int nbase = ((warp >> 2) & 1) * 32;
    const int kh    = warp >> 3;        // k-half: ksteps {2kh, 2kh+1}
    const int rl    = lane & 15;
    const int cb    = lane >> 4;
    const int arx   = rl & 7;
    const int browl = (lane & 7) + ((lane & 16) >> 1);
    const int bcb   = (lane >> 3) & 1;
    const int bxor  = lane & 7;

    float acc[2][4][4];
    #pragma unroll
    for (int mt = 0; mt < 2; ++mt)
        #pragma unroll
        for (int nt = 0; nt < 4; ++nt)
            #pragma unroll
            for (int r = 0; r < 4; ++r) acc[mt][nt][r] = 0.f;

    // ---- prologue: stage chunk 0, prefetch chunk 1 LDG ----
    load_v(v, x, tok0, 0, kq, rowbase);
    #pragma unroll
    for (int i = 0; i < 2; ++i) {
        int lin = i * NTHREADS + tid;
        cp16s(sb + A_REGION + lin * 16, g_w_sw + lin * 16);
    }
    cp_commit();
    stage_x(smem_raw, v, kq, rowbase);
    load_v(v, x, tok0, HC, kq, rowbase);
    cp_wait0();
    __syncthreads();

    for (int c = 0; c < NCHUNKS; ++c) {
        // ---- stage chunk c+1 into the other buffer ----
        if (c + 1 < NCHUNKS) {
            unsigned char* nbuf = smem_raw + ((c + 1) & 1) * BUF_BYTES;
            const uint32_t nbufu = sb + ((c + 1) & 1) * BUF_BYTES;
            const unsigned char* src = g_w_sw + (size_t)(c + 1) * W_CHUNK_BYTES;
            #pragma unroll
            for (int i = 0; i < 2; ++i) {
                int lin = i * NTHREADS + tid;
                cp16s(nbufu + A_REGION + lin * 16, src + lin * 16);
            }
            cp_commit();
            stage_x(nbuf, v, kq, rowbase);
        }
        if (c + 2 < NCHUNKS)
            load_v(v, x, tok0, (c + 2) * HC, kq, rowbase);

        // ---- compute chunk c: this warp's 2 ksteps x 3 fp16-split products ----
        const uint32_t Ab = sb + (c & 1) * BUF_BYTES;
        const uint32_t Bb = Ab + A_REGION;
        const uint32_t a_row = Ab + (mbase + rl) * 128;
        const uint32_t b_row = Bb + (nbase + browl) * 128;
        #pragma unroll
        for (int j = 0; j < 2; ++j) {
            const int ks = 2 * kh + j;
            uint32_t bf[2][8];
            const uint32_t bcol = (uint32_t)(((2 * ks + bcb) ^ bxor) * 16);
            #pragma unroll
            for (int s = 0; s < 2; ++s) {
                ldm4(bf[s][0], bf[s][1], bf[s][2], bf[s][3],
                     b_row + s * B_SPLIT + bcol);
                ldm4(bf[s][4], bf[s][5], bf[s][6], bf[s][7],
                     b_row + s * B_SPLIT + 2048 + bcol);
            }
            uint32_t af[2][2][4];
            const uint32_t acol = (uint32_t)(((2 * ks + cb) ^ arx) * 16);
            #pragma unroll
            for (int s = 0; s < 2; ++s)
                #pragma unroll
                for (int mt = 0; mt < 2; ++mt)
                    ldm4(af[s][mt][0], af[s][mt][1], af[s][mt][2], af[s][mt][3],
                         a_row + s * A_SPLIT + mt * 2048 + acol);
            // products: x1*w1, x1*w2, x2*w1
            #pragma unroll
            for (int p = 0; p < 3; ++p) {
                const int sa = (p == 2) ? 1 : 0;
                const int sbi = (p == 1) ? 1 : 0;
                #pragma unroll
                for (int mt = 0; mt < 2; ++mt)
                    #pragma unroll
                    for (int nt = 0; nt < 4; ++nt)
                        mma16816(acc[mt][nt], af[sa][mt], &bf[sbi][nt * 2]);
            }
        }
        cp_wait0();
        __syncthreads();
    }

    // ---- epilogue: combine k-halves into smem logits [128][68] ----
    float* ls = reinterpret_cast<float*>(smem_raw);
    if (kh == 0) {
        #pragma unroll
        for (int mt = 0; mt < 2; ++mt) {
            int row0 = mbase + mt * 16 + (lane >> 2);
            #pragma unroll
            for (int nt = 0; nt < 4; ++nt) {
                int col = nbase + nt * 8 + (lane & 3) * 2;
                *reinterpret_cast<float2*>(&ls[row0 * 68 + col]) =
                    make_float2(acc[mt][nt][0], acc[mt][nt][1]);
                *reinterpret_cast<float2*>(&ls[(row0 + 8) * 68 + col]) =
                    make_float2(acc[mt][nt][2], acc[mt][nt][3]);
            }
        }
    }
    __syncthreads();
    if (kh == 1) {
        #pragma unroll
        for (int mt = 0; mt < 2; ++mt) {
            int row0 = mbase + mt * 16 + (lane >> 2);
            #pragma unroll
            for (int nt = 0; nt < 4; ++nt) {
                int col = nbase + nt * 8 + (lane & 3) * 2;
                float2 a = *reinterpret_cast<float2*>(&ls[row0 * 68 + col]);
                *reinterpret_cast<float2*>(&ls[row0 * 68 + col]) =
                    make_float2(a.x + acc[mt][nt][0], a.y + acc[mt][nt][1]);
                float2 b = *reinterpret_cast<float2*>(&ls[(row0 + 8) * 68 + col]);
                *reinterpret_cast<float2*>(&ls[(row0 + 8) * 68 + col]) =
                    make_float2(b.x + acc[mt][nt][2], b.y + acc[mt][nt][3]);
            }
        }
    }
    __syncthreads();

    // one thread per token: top-2 + softmax scores + z partial (descale by 1/64)
    float zsum = 0.f;
    if (tid < 128) {
        const float* row = &ls[tid * 68];
        float m = -3.402823466e38f; int i1 = 0;
        #pragma unroll 8
        for (int e = 0; e < EXP; ++e) {
            float vv = row[e] * INV_WSCALE;
            if (vv > m) { m = vv; i1 = e; }
        }
        float m2 = -3.402823466e38f; int i2 = 0;
        #pragma unroll 8
        for (int e = 0; e < EXP; ++e) {
            if (e == i1) continue;
            float vv = row[e] * INV_WSCALE;
            if (vv > m2) { m2 = vv; i2 = e; }
        }
        float Z = 0.f;
        #pragma unroll 8
        for (int e = 0; e < EXP; ++e) {
            float vv = row[e] * INV_WSCALE;
            Z += expf(vv - m);
            zsum += vv * vv;
        }
        int g = tok0 + tid;
        out[2 * g]     = (float)i1;
        out[2 * g + 1] = (float)i2;
        out[2 * T + 2 * g]     = 1.0f / Z;
        out[2 * T + 2 * g + 1] = expf(m2 - m) / Z;
    }

    // deterministic block reduce of z partial
    __shared__ float zred[NTHREADS];
    __shared__ unsigned int s_last;
    zred[tid] = zsum;
    __syncthreads();
    #pragma unroll
    for (int s = NTHREADS / 2; s > 0; s >>= 1) {
        if (tid < s) zred[tid] += zred[tid + s];
        __syncthreads();
    }
    if (tid == 0) {
        g_partials[blockIdx.x] = zred[0];
        __threadfence();
        unsigned prev = atomicAdd(&g_done, 1u);
        s_last = (prev == gridDim.x - 1) ? 1u : 0u;
    }
    __syncthreads();

    // last block finalizes (deterministic fixed-order tree over g_partials)
    if (s_last) {
        __threadfence();
        float pv = (tid < (int)gridDim.x) ? g_partials[tid] : 0.f;
        zred[tid] = pv;
        __syncthreads();
        #pragma unroll
        for (int s = NTHREADS / 2; s > 0; s >>= 1) {
            if (tid < s) zred[tid] += zred[tid + s];
            __syncthreads();
        }
        if (tid == 0) {
            out[4 * T]     = 0.0f;                       // aux_loss
            out[4 * T + 1] = zred[0] / (float)(T * EXP); // z_loss
            g_done = 0;                                  // reset for graph replay
        }
    }
}

extern "C" void kernel_launch(void* const* d_in, const int* in_sizes, int n_in,
                              void* d_out, int out_size) {
    const float* x  = (const float*)d_in[0];
    const float* gw = (const float*)d_in[1];
    float* out = (float*)d_out;

    int T = in_sizes[0] / HDIM;            // 16384
    int blocks = T / TOK_PER_BLK;          // 128

    cudaFuncSetAttribute(router_kernel,
                         cudaFuncAttributeMaxDynamicSharedMemorySize, SMEM_TOTAL);

    prep_w<<<512, 256>>>(gw);
    router_kernel<<<blocks, NTHREADS, SMEM_TOTAL>>>(x, out, T);
}

// round 12
// speedup vs baseline: 1.2451x; 1.2451x over previous
#include <cuda_runtime.h>
#include <cuda_fp16.h>
#include <cstdint>

// B=4, S=4096, H=4096, E=64, topK=2 -> T=16384 tokens
#define HDIM 4096
#define EXP  64
#define HC   64                        // K per pipeline chunk
#define NCHUNKS (HDIM / HC)            // 64
#define TOK_PER_BLK 128
#define NTHREADS 384                   // warps 0-7 consumers, 8-11 producers

#define A_SPLIT 16384                  // 128 rows x 128 B (64 fp16) SW128
#define B_SPLIT 8192                   // 64 rows x 128 B SW128
#define A_REGION (2 * A_SPLIT)         // 32768
#define B_REGION (2 * B_SPLIT)         // 16384
#define W_CHUNK_BYTES B_REGION
#define BUF_BYTES (A_REGION + B_REGION)        // 49152
#define SMEM_TOTAL (2 * BUF_BYTES)             // 98304

#define WSCALE 64.0f
#define INV_WSCALE 0.015625f

__device__ float g_partials[256];
__device__ unsigned int g_done;
__device__ unsigned char g_w_sw[NCHUNKS * W_CHUNK_BYTES];  // 1 MB, L2-resident

// ---------------- helpers ----------------
__device__ __forceinline__ unsigned sw128(unsigned off) {
    return off ^ ((off >> 3) & 0x70);
}
__device__ __forceinline__ uint32_t h2u(__half2 h) {
    return *reinterpret_cast<uint32_t*>(&h);
}
__device__ __forceinline__ void cp16s(uint32_t dst, const void* src) {
    asm volatile("cp.async.cg.shared.global [%0], [%1], 16;" :: "r"(dst), "l"(src));
}
__device__ __forceinline__ void cp_commit() { asm volatile("cp.async.commit_group;"); }
__device__ __forceinline__ void cp_wait0()  { asm volatile("cp.async.wait_group 0;"); }

__device__ __forceinline__ void ldm4(uint32_t& r0, uint32_t& r1, uint32_t& r2,
                                     uint32_t& r3, uint32_t addr) {
    asm volatile("ldmatrix.sync.aligned.m8n8.x4.shared.b16 {%0,%1,%2,%3}, [%4];"
                 : "=r"(r0), "=r"(r1), "=r"(r2), "=r"(r3) : "r"(addr));
}
__device__ __forceinline__ void mma16816(float* d, const uint32_t* a, const uint32_t* b) {
    asm volatile(
        "mma.sync.aligned.m16n8k16.row.col.f32.f16.f16.f32 "
        "{%0,%1,%2,%3}, {%4,%5,%6,%7}, {%8,%9}, {%0,%1,%2,%3};"
        : "+f"(d[0]), "+f"(d[1]), "+f"(d[2]), "+f"(d[3])
        : "r"(a[0]), "r"(a[1]), "r"(a[2]), "r"(a[3]), "r"(b[0]), "r"(b[1]));
}

// ---------------- prologue: fp16 2-split of (gate_w * 64), SW128, per chunk ----------------
__global__ void prep_w(const float* __restrict__ gw) {
    int idx = blockIdx.x * blockDim.x + threadIdx.x;   // 64c * 64e * 32kp = 131072
    int kp = idx & 31;
    int e  = (idx >> 5) & 63;
    int c  = idx >> 11;
    float2 v = *reinterpret_cast<const float2*>(&gw[(size_t)e * HDIM + c * HC + kp * 2]);
    float ax = v.x * WSCALE, ay = v.y * WSCALE;
    unsigned off = sw128((unsigned)(e * 128 + kp * 4));
    unsigned char* base = g_w_sw + (size_t)c * W_CHUNK_BYTES;
    __half2 h1 = __floats2half2_rn(ax, ay);
    *reinterpret_cast<uint32_t*>(base + off) = h2u(h1);
    float2 f1 = __half22float2(h1);
    __half2 h2 = __floats2half2_rn(ax - f1.x, ay - f1.y);
    *reinterpret_cast<uint32_t*>(base + B_SPLIT + off) = h2u(h2);
}

// ---------------- producer staging (128 threads: 16 rows each) ----------------
__device__ __forceinline__ void load_v(float4* v, const float* __restrict__ x,
                                       int tok0, int k0, int kq, int rowbase) {
    #pragma unroll
    for (int i = 0; i < 16; ++i)
        v[i] = *reinterpret_cast<const float4*>(
            &x[(size_t)(tok0 + rowbase + 8 * i) * HDIM + k0 + kq * 4]);
}
__device__ __forceinline__ void stage_x(unsigned char* buf, const float4* v,
                                        int kq, int rowbase) {
    #pragma unroll
    for (int i = 0; i < 16; ++i) {
        int r = rowbase + 8 * i;
        unsigned off = sw128((unsigned)(r * 128 + kq * 8));
        __half2 h1a = __floats2half2_rn(v[i].x, v[i].y);
        __half2 h1b = __floats2half2_rn(v[i].z, v[i].w);
        *reinterpret_cast<uint2*>(buf + off) = make_uint2(h2u(h1a), h2u(h1b));
        float2 f1a = __half22float2(h1a);
        float2 f1b = __half22float2(h1b);
        __half2 h2a = __floats2half2_rn(v[i].x - f1a.x, v[i].y - f1a.y);
        __half2 h2b = __floats2half2_rn(v[i].z - f1b.x, v[i].w - f1b.y);
        *reinterpret_cast<uint2*>(buf + A_SPLIT + off) = make_uint2(h2u(h2a), h2u(h2b));
    }
}

// ---------------- main fused router ----------------
extern __shared__ unsigned char smem_raw[];

__global__ __launch_bounds__(NTHREADS, 1)
void router_kernel(const float* __restrict__ x, float* __restrict__ out, int T) {
    const int tid  = threadIdx.x;
    const int lane = tid & 31;
    const int warp = tid >> 5;          // 0..11
    const int tok0 = blockIdx.x * TOK_PER_BLK;
    const uint32_t sb = (uint32_t)__cvta_generic_to_shared(smem_raw);

    if (warp >= 8) {
        // ================= PRODUCER warps 8-11 =================
        const int ptid    = tid - 256;      // 0..127
        const int kq      = ptid & 15;
        const int rowbase = ptid >> 4;      // 0..7
        float4 v[16];

        // prologue: stage chunk 0, prefetch chunk 1
        load_v(v, x, tok0, 0, kq, rowbase);
        #pragma unroll
        for (int i = 0; i < 8; ++i) {
            int lin = i * 128 + ptid;
            cp16s(sb + A_REGION + lin * 16, g_w_sw + lin * 16);
        }
        cp_commit();
        stage_x(smem_raw, v, kq, rowbase);
        load_v(v, x, tok0, HC, kq, rowbase);
        cp_wait0();
        __syncthreads();

        for (int c = 0; c < NCHUNKS; ++c) {
            if (c + 1 < NCHUNKS) {
                unsigned char* nbuf = smem_raw + ((c + 1) & 1) * BUF_BYTES;
                const uint32_t nbufu = sb + ((c + 1) & 1) * BUF_BYTES;
                const unsigned char* src = g_w_sw + (size_t)(c + 1) * W_CHUNK_BYTES;
                #pragma unroll
                for (int i = 0; i < 8; ++i) {
                    int lin = i * 128 + ptid;
                    cp16s(nbufu + A_REGION + lin * 16, src + lin * 16);
                }
                cp_commit();
                stage_x(nbuf, v, kq, rowbase);
                if (c + 2 < NCHUNKS)
                    load_v(v, x, tok0, (c + 2) * HC, kq, rowbase);
                cp_wait0();
            }
            __syncthreads();
        }

        // join epilogue barriers (no logits work)
        __syncthreads();
        __syncthreads();
    } else {
        // ================= CONSUMER warps 0-7 =================
        const int mbase = (warp & 3) * 32;
        const int nbase = (warp >> 2) * 32;
        const int rl    = lane & 15;
        const int cb    = lane >> 4;
        const int arx   = rl & 7;
        const int browl = (lane & 7) + ((lane & 16) >> 1);
        const int bcb   = (lane >> 3) & 1;
        const int bxor  = lane & 7;

        float acc[2][4][4];
        #pragma unroll
        for (int mt = 0; mt < 2; ++mt)
            #pragma unroll
            for (int nt = 0; nt < 4; ++nt)
                #pragma unroll
                for (int r = 0; r < 4; ++r) acc[mt][nt][r] = 0.f;

        __syncthreads();  // wait chunk 0 staged

        uint32_t bf[2][2][8];      // [pipe][split][frag]
        uint32_t af[2][2][2][4];   // [pipe][split][mt][frag]

        for (int c = 0; c < NCHUNKS; ++c) {
            const uint32_t Ab = sb + (c & 1) * BUF_BYTES;
            const uint32_t Bb = Ab + A_REGION;
            const uint32_t a_row = Ab + (mbase + rl) * 128;
            const uint32_t b_row = Bb + (nbase + browl) * 128;

            // preload kstep 0 fragments
            {
                const uint32_t bcol = (uint32_t)((bcb ^ bxor) * 16);
                const uint32_t acol = (uint32_t)((cb ^ arx) * 16);
                #pragma unroll
                for (int s = 0; s < 2; ++s) {
                    ldm4(bf[0][s][0], bf[0][s][1], bf[0][s][2], bf[0][s][3],
                         b_row + s * B_SPLIT + bcol);
                    ldm4(bf[0][s][4], bf[0][s][5], bf[0][s][6], bf[0][s][7],
                         b_row + s * B_SPLIT + 2048 + bcol);
                    #pragma unroll
                    for (int mt = 0; mt < 2; ++mt)
                        ldm4(af[0][s][mt][0], af[0][s][mt][1],
                             af[0][s][mt][2], af[0][s][mt][3],
                             a_row + s * A_SPLIT + mt * 2048 + acol);
                }
            }

            #pragma unroll
            for (int ks = 0; ks < 4; ++ks) {
                const int cur = ks & 1, nxt = cur ^ 1;
                if (ks < 3) {  // preload ks+1 while issuing MMAs for ks
                    const uint32_t bcol = (uint32_t)(((2 * (ks + 1) + bcb) ^ bxor) * 16);
                    const uint32_t acol = (uint32_t)(((2 * (ks + 1) + cb) ^ arx) * 16);
                    #pragma unroll
                    for (int s = 0; s < 2; ++s) {
                        ldm4(bf[nxt][s][0], bf[nxt][s][1], bf[nxt][s][2], bf[nxt][s][3],
                             b_row + s * B_SPLIT + bcol);
                        ldm4(bf[nxt][s][4], bf[nxt][s][5], bf[nxt][s][6], bf[nxt][s][7],
                             b_row + s * B_SPLIT + 2048 + bcol);
                        #pragma unroll
                        for (int mt = 0; mt < 2; ++mt)
                            ldm4(af[nxt][s][mt][0], af[nxt][s][mt][1],
                                 af[nxt][s][mt][2], af[nxt][s][mt][3],
                                 a_row + s * A_SPLIT + mt * 2048 + acol);
                    }
                }
                // products: x1*w1, x1*w2, x2*w1
                #pragma unroll
                for (int p = 0; p < 3; ++p) {
                    const int sa = (p == 2) ? 1 : 0;
                    const int sbi = (p == 1) ? 1 : 0;
                    #pragma unroll
                    for (int mt = 0; mt < 2; ++mt)
                        #pragma unroll
                        for (int nt = 0; nt < 4; ++nt)
                            mma16816(acc[mt][nt], af[cur][sa][mt], &bf[cur][sbi][nt * 2]);
                }
            }
            __syncthreads();
        }

        // ---- epilogue: descaled logits -> smem [128][68] ----
        float* ls = reinterpret_cast<float*>(smem_raw);
        #pragma unroll
        for (int mt = 0; mt < 2; ++mt) {
            int row0 = mbase + mt * 16 + (lane >> 2);
            #pragma unroll
            for (int nt = 0; nt < 4; ++nt) {
                int col = nbase + nt * 8 + (lane & 3) * 2;
                *reinterpret_cast<float2*>(&ls[row0 * 68 + col]) =
                    make_float2(acc[mt][nt][0] * INV_WSCALE, acc[mt][nt][1] * INV_WSCALE);
                *reinterpret_cast<float2*>(&ls[(row0 + 8) * 68 + col]) =
                    make_float2(acc[mt][nt][2] * INV_WSCALE, acc[mt][nt][3] * INV_WSCALE);
            }
        }
        __syncthreads();

        // one thread per token: top-2 + softmax + z partial
        float zsum = 0.f;
        if (tid < 128) {
            const float* row = &ls[tid * 68];
            float m = -3.402823466e38f; int i1 = 0;
            #pragma unroll 8
            for (int e = 0; e < EXP; ++e) {
                float vv = row[e];
                if (vv > m) { m = vv; i1 = e; }
            }
            float m2 = -3.402823466e38f; int i2 = 0;
            #pragma unroll 8
            for (int e = 0; e < EXP; ++e) {
                if (e == i1) continue;
                float vv = row[e];
                if (vv > m2) { m2 = vv; i2 = e; }
            }
            float Z = 0.f;
            #pragma unroll 8
            for (int e = 0; e < EXP; ++e) {
                float vv = row[e];
                Z += expf(vv - m);
                zsum += vv * vv;
            }
            int g = tok0 + tid;
            out[2 * g]     = (float)i1;
            out[2 * g + 1] = (float)i2;
            out[2 * T + 2 * g]     = 1.0f / Z;
            out[2 * T + 2 * g + 1] = expf(m2 - m) / Z;
        }
        // stash z partial in ls row area past logits (col region unused: use smem_raw + BUF_BYTES)
        reinterpret_cast<float*>(smem_raw + BUF_BYTES)[tid] = zsum;
        __syncthreads();
    }

    // ---- shared tail: deterministic z reduce (first 128 entries hold partials) ----
    float* zred = reinterpret_cast<float*>(smem_raw + BUF_BYTES);
    __shared__ unsigned int s_last;
    // producers didn't write: entries 256..383 unwritten; only 0..127 matter.
    __syncthreads();
    #pragma unroll
    for (int s = 64; s > 0; s >>= 1) {
        if (tid < s) zred[tid] += zred[tid + s];
        __syncthreads();
    }
    if (tid == 0) {
        g_partials[blockIdx.x] = zred[0];
        __threadfence();
        unsigned prev = atomicAdd(&g_done, 1u);
        s_last = (prev == gridDim.x - 1) ? 1u : 0u;
    }
    __syncthreads();

    if (s_last) {
        __threadfence();
        if (tid < 128) zred[tid] = g_partials[tid];
        __syncthreads();
        #pragma unroll
        for (int s = 64; s > 0; s >>= 1) {
            if (tid < s) zred[tid] += zred[tid + s];
            __syncthreads();
        }
        if (tid == 0) {
            out[4 * T]     = 0.0f;                       // aux_loss
            out[4 * T + 1] = zred[0] / (float)(T * EXP); // z_loss
            g_done = 0;                                  // reset for graph replay
        }
    }
}

extern "C" void kernel_launch(void* const* d_in, const int* in_sizes, int n_in,
                              void* d_out, int out_size) {
    const float* x  = (const float*)d_in[0];
    const float* gw = (const float*)d_in[1];
    float* out = (float*)d_out;

    int T = in_sizes[0] / HDIM;            // 16384
    int blocks = T / TOK_PER_BLK;          // 128

    cudaFuncSetAttribute(router_kernel,
                         cudaFuncAttributeMaxDynamicSharedMemorySize, SMEM_TOTAL);

    prep_w<<<512, 256>>>(gw);
    router_kernel<<<blocks, NTHREADS, SMEM_TOTAL>>>(x, out, T);
}